// round 1
// baseline (speedup 1.0000x reference)
#include <cuda_runtime.h>
#include <math.h>

#define BB 2
#define HH 720
#define WW 1280
#define HW (HH*WW)
#define NPIX (BB*HW)
#define EPSF 1e-7f

// Scratch: splat accumulators [dir][b][pixel][4ch]  (~59 MB), raw masks (~14.7 MB)
__device__ __align__(16) float g_acc[(size_t)2 * BB * HW * 4];
__device__ float g_mask[(size_t)2 * BB * HW];

// ---------------------------------------------------------------------------
// Splat kernel: each thread handles one source pixel, both warp directions.
// dir 0 (f01): img0 splat with 0.5*flow1 (channels swapped: fx uses flow ch1),
//              weight exp(z1).
// dir 1 (f10): img1 splat with 0.5*flow0, weight exp(z0).
// ---------------------------------------------------------------------------
__global__ void __launch_bounds__(256) splat_kernel(
    const float* __restrict__ img0, const float* __restrict__ img1,
    const float* __restrict__ flow0, const float* __restrict__ flow1,
    const float* __restrict__ z0, const float* __restrict__ z1)
{
    int i = blockIdx.x * blockDim.x + threadIdx.x;
    if (i >= NPIX) return;
    int b = i / HW;
    int p = i - b * HW;
    int y = p / WW;
    int x = p - y * WW;

#pragma unroll
    for (int d = 0; d < 2; ++d) {
        const float* img = d ? img1 : img0;
        const float* fl  = d ? flow0 : flow1;
        const float* zz  = d ? z0 : z1;

        float fx = (float)x + 0.5f * fl[(size_t)(b * 2 + 1) * HW + p];
        float fy = (float)y + 0.5f * fl[(size_t)(b * 2 + 0) * HW + p];
        float w  = expf(zz[(size_t)b * HW + p]);
        float vr = img[(size_t)(b * 3 + 0) * HW + p] * w;
        float vg = img[(size_t)(b * 3 + 1) * HW + p] * w;
        float vb = img[(size_t)(b * 3 + 2) * HW + p] * w;

        float x0f = floorf(fx), y0f = floorf(fy);
        int ix0 = (int)x0f, iy0 = (int)y0f;
        float ax = fx - x0f, ay = fy - y0f;

        float* acc = g_acc + (size_t)(d * BB + b) * HW * 4;
#pragma unroll
        for (int cy = 0; cy < 2; ++cy) {
            int ty = iy0 + cy;
            if ((unsigned)ty >= (unsigned)HH) continue;
            float wy = cy ? ay : (1.0f - ay);
#pragma unroll
            for (int cx = 0; cx < 2; ++cx) {
                int tx = ix0 + cx;
                if ((unsigned)tx >= (unsigned)WW) continue;
                float wt = wy * (cx ? ax : (1.0f - ax));
                float* a = acc + ((size_t)ty * WW + tx) * 4;
                atomicAdd(a + 0, vr * wt);
                atomicAdd(a + 1, vg * wt);
                atomicAdd(a + 2, vb * wt);
                atomicAdd(a + 3, w  * wt);
            }
        }
    }
}

// ---------------------------------------------------------------------------
// Normalize: f01i -> out ch6..8, f10i -> ch9..11, flows*0.5 -> ch12..15,
// raw masks s/(s+eps) -> g_mask.
// ---------------------------------------------------------------------------
__global__ void __launch_bounds__(256) normalize_kernel(
    const float* __restrict__ flow0, const float* __restrict__ flow1,
    float* __restrict__ out)
{
    int i = blockIdx.x * blockDim.x + threadIdx.x;
    if (i >= NPIX) return;
    int b = i / HW;
    int p = i - b * HW;

    const float4* acc01 = reinterpret_cast<const float4*>(g_acc) + (size_t)(0 * BB + b) * HW;
    const float4* acc10 = reinterpret_cast<const float4*>(g_acc) + (size_t)(1 * BB + b) * HW;
    float4 a0 = acc01[p];
    float4 a1 = acc10[p];
    float i0 = 1.0f / (a0.w + EPSF);
    float i1 = 1.0f / (a1.w + EPSF);

    float* ob = out + (size_t)b * 18 * HW;
    ob[(size_t)6  * HW + p] = a0.x * i0;
    ob[(size_t)7  * HW + p] = a0.y * i0;
    ob[(size_t)8  * HW + p] = a0.z * i0;
    ob[(size_t)9  * HW + p] = a1.x * i1;
    ob[(size_t)10 * HW + p] = a1.y * i1;
    ob[(size_t)11 * HW + p] = a1.z * i1;
    ob[(size_t)12 * HW + p] = 0.5f * flow0[(size_t)(b * 2 + 0) * HW + p];
    ob[(size_t)13 * HW + p] = 0.5f * flow0[(size_t)(b * 2 + 1) * HW + p];
    ob[(size_t)14 * HW + p] = 0.5f * flow1[(size_t)(b * 2 + 0) * HW + p];
    ob[(size_t)15 * HW + p] = 0.5f * flow1[(size_t)(b * 2 + 1) * HW + p];

    g_mask[(size_t)(0 * BB + b) * HW + p] = a0.w * i0;
    g_mask[(size_t)(1 * BB + b) * HW + p] = a1.w * i1;
}

// ---------------------------------------------------------------------------
// Fused morphological open (erode kxk then dilate kxk, SAME padding,
// inf/-inf pad values) + final compose. Separable min/max in shared memory.
// One block = one 32x16 output tile, processes BOTH masks (m=0: f01m, m=1: f10m).
// ---------------------------------------------------------------------------
#define TTX 32
#define TTY 16
#define RMAX 4
#define INW_MAX (TTX + 4 * RMAX)   // 48
#define INH_MAX (TTY + 4 * RMAX)   // 32
#define HMW_MAX (TTX + 2 * RMAX)   // 40
#define EH_MAX  (TTY + 2 * RMAX)   // 24

__global__ void __launch_bounds__(TTX * TTY) open_compose_kernel(
    const int* __restrict__ kptr, float* __restrict__ out)
{
    __shared__ float s_in[2][INH_MAX][INW_MAX];
    __shared__ float s_hm[2][INH_MAX][HMW_MAX];
    __shared__ float s_er[2][EH_MAX][HMW_MAX];
    __shared__ float s_hx[2][EH_MAX][TTX];

    const float PINF = __int_as_float(0x7f800000);
    const float NINF = __int_as_float(0xff800000);

    int kk = kptr[0];
    int r = (kk >= 2) ? (kk - 1) / 2 : 0;
    if (r > RMAX) r = RMAX;

    int b  = blockIdx.z;
    int ox = blockIdx.x * TTX;
    int oy = blockIdx.y * TTY;
    int tid = threadIdx.y * TTX + threadIdx.x;
    const int NT = TTX * TTY;

    int inw = TTX + 4 * r, inh = TTY + 4 * r;
    int hmw = TTX + 2 * r, eh = TTY + 2 * r;
    int win = 2 * r;  // extra taps beyond center

    // Load masks (+inf outside image: erosion pad value)
    for (int idx = tid; idx < 2 * inh * inw; idx += NT) {
        int m = idx / (inh * inw);
        int rem = idx - m * inh * inw;
        int iy = rem / inw;
        int ix = rem - iy * inw;
        int gy = oy - 2 * r + iy;
        int gx = ox - 2 * r + ix;
        float v = PINF;
        if ((unsigned)gy < (unsigned)HH && (unsigned)gx < (unsigned)WW)
            v = g_mask[(size_t)(m * BB + b) * HW + (size_t)gy * WW + gx];
        s_in[m][iy][ix] = v;
    }
    __syncthreads();

    // Horizontal min
    for (int idx = tid; idx < 2 * inh * hmw; idx += NT) {
        int m = idx / (inh * hmw);
        int rem = idx - m * inh * hmw;
        int iy = rem / hmw;
        int hx = rem - iy * hmw;
        float v = s_in[m][iy][hx];
        for (int dd = 1; dd <= win; ++dd) v = fminf(v, s_in[m][iy][hx + dd]);
        s_hm[m][iy][hx] = v;
    }
    __syncthreads();

    // Vertical min -> erosion; out-of-image positions become -inf (dilation pad)
    for (int idx = tid; idx < 2 * eh * hmw; idx += NT) {
        int m = idx / (eh * hmw);
        int rem = idx - m * eh * hmw;
        int ey = rem / hmw;
        int hx = rem - ey * hmw;
        int gy = oy - r + ey;
        int gx = ox - r + hx;
        float v = NINF;
        if ((unsigned)gy < (unsigned)HH && (unsigned)gx < (unsigned)WW) {
            v = s_hm[m][ey][hx];
            for (int dd = 1; dd <= win; ++dd) v = fminf(v, s_hm[m][ey + dd][hx]);
        }
        s_er[m][ey][hx] = v;
    }
    __syncthreads();

    // Horizontal max
    for (int idx = tid; idx < 2 * eh * TTX; idx += NT) {
        int m = idx / (eh * TTX);
        int rem = idx - m * eh * TTX;
        int ey = rem / TTX;
        int xx = rem - ey * TTX;
        float v = s_er[m][ey][xx];
        for (int dd = 1; dd <= win; ++dd) v = fmaxf(v, s_er[m][ey][xx + dd]);
        s_hx[m][ey][xx] = v;
    }
    __syncthreads();

    // Vertical max -> opened masks; then compose and write output
    int txx = threadIdx.x, tyy = threadIdx.y;
    int gx = ox + txx, gy = oy + tyy;
    if (gx < WW && gy < HH) {
        float m01 = s_hx[0][tyy][txx];
        float m10 = s_hx[1][tyy][txx];
        for (int dd = 1; dd <= win; ++dd) {
            m01 = fmaxf(m01, s_hx[0][tyy + dd][txx]);
            m10 = fmaxf(m10, s_hx[1][tyy + dd][txx]);
        }
        size_t p = (size_t)gy * WW + gx;
        float* ob = out + (size_t)b * 18 * HW;
        float f01r = ob[(size_t)6  * HW + p];
        float f01g = ob[(size_t)7  * HW + p];
        float f01b = ob[(size_t)8  * HW + p];
        float f10r = ob[(size_t)9  * HW + p];
        float f10g = ob[(size_t)10 * HW + p];
        float f10b = ob[(size_t)11 * HW + p];
        ob[(size_t)0 * HW + p] = m01 * f01r + (1.0f - m01) * f10r;
        ob[(size_t)1 * HW + p] = m01 * f01g + (1.0f - m01) * f10g;
        ob[(size_t)2 * HW + p] = m01 * f01b + (1.0f - m01) * f10b;
        ob[(size_t)3 * HW + p] = m10 * f10r + (1.0f - m10) * f01r;
        ob[(size_t)4 * HW + p] = m10 * f10g + (1.0f - m10) * f01g;
        ob[(size_t)5 * HW + p] = m10 * f10b + (1.0f - m10) * f01b;
        ob[(size_t)16 * HW + p] = m01;
        ob[(size_t)17 * HW + p] = m10;
    }
}

// ---------------------------------------------------------------------------
extern "C" void kernel_launch(void* const* d_in, const int* in_sizes, int n_in,
                              void* d_out, int out_size)
{
    const float* img0  = (const float*)d_in[0];
    const float* img1  = (const float*)d_in[1];
    const float* flow0 = (const float*)d_in[2];
    const float* flow1 = (const float*)d_in[3];
    const float* z0    = (const float*)d_in[4];
    const float* z1    = (const float*)d_in[5];
    const int*   kptr  = (const int*)d_in[6];
    float* out = (float*)d_out;

    // Clear accumulators (memset node in the captured graph)
    void* accPtr = nullptr;
    cudaGetSymbolAddress(&accPtr, g_acc);
    cudaMemsetAsync(accPtr, 0, sizeof(float) * (size_t)2 * BB * HW * 4, 0);

    int threads = 256;
    int blocks = (NPIX + threads - 1) / threads;
    splat_kernel<<<blocks, threads>>>(img0, img1, flow0, flow1, z0, z1);
    normalize_kernel<<<blocks, threads>>>(flow0, flow1, out);

    dim3 gblk(TTX, TTY, 1);
    dim3 ggrid((WW + TTX - 1) / TTX, (HH + TTY - 1) / TTY, BB);
    open_compose_kernel<<<ggrid, gblk>>>(kptr, out);
}

// round 2
// speedup vs baseline: 2.1984x; 2.1984x over previous
#include <cuda_runtime.h>
#include <math.h>

#define BB 2
#define HH 720
#define WW 1280
#define HW (HH*WW)
#define NPIX (BB*HW)
#define EPSF 1e-7f

// Scratch: splat accumulators [dir][b][pixel][4ch]  (~59 MB)
__device__ __align__(16) float g_acc[(size_t)2 * BB * HW * 4];

// ---------------------------------------------------------------------------
// Splat kernel: each thread handles one source pixel, both warp directions.
// Uses sm_90+ float4 atomicAdd -> one RED.E.128 per corner (4x fewer REDs).
// ---------------------------------------------------------------------------
__global__ void __launch_bounds__(256) splat_kernel(
    const float* __restrict__ img0, const float* __restrict__ img1,
    const float* __restrict__ flow0, const float* __restrict__ flow1,
    const float* __restrict__ z0, const float* __restrict__ z1)
{
    int i = blockIdx.x * blockDim.x + threadIdx.x;
    if (i >= NPIX) return;
    int b = i / HW;
    int p = i - b * HW;
    int y = p / WW;
    int x = p - y * WW;

#pragma unroll
    for (int d = 0; d < 2; ++d) {
        const float* img = d ? img1 : img0;
        const float* fl  = d ? flow0 : flow1;
        const float* zz  = d ? z0 : z1;

        float fx = (float)x + 0.5f * fl[(size_t)(b * 2 + 1) * HW + p];
        float fy = (float)y + 0.5f * fl[(size_t)(b * 2 + 0) * HW + p];
        float w  = expf(zz[(size_t)b * HW + p]);
        float vr = img[(size_t)(b * 3 + 0) * HW + p] * w;
        float vg = img[(size_t)(b * 3 + 1) * HW + p] * w;
        float vb = img[(size_t)(b * 3 + 2) * HW + p] * w;

        float x0f = floorf(fx), y0f = floorf(fy);
        int ix0 = (int)x0f, iy0 = (int)y0f;
        float ax = fx - x0f, ay = fy - y0f;

        float4* acc = reinterpret_cast<float4*>(g_acc) + (size_t)(d * BB + b) * HW;
#pragma unroll
        for (int cy = 0; cy < 2; ++cy) {
            int ty = iy0 + cy;
            if ((unsigned)ty >= (unsigned)HH) continue;
            float wy = cy ? ay : (1.0f - ay);
#pragma unroll
            for (int cx = 0; cx < 2; ++cx) {
                int tx = ix0 + cx;
                if ((unsigned)tx >= (unsigned)WW) continue;
                float wt = wy * (cx ? ax : (1.0f - ax));
#if __CUDA_ARCH__ >= 900
                atomicAdd(acc + ((size_t)ty * WW + tx),
                          make_float4(vr * wt, vg * wt, vb * wt, w * wt));
#else
                float* a = reinterpret_cast<float*>(acc + ((size_t)ty * WW + tx));
                atomicAdd(a + 0, vr * wt);
                atomicAdd(a + 1, vg * wt);
                atomicAdd(a + 2, vb * wt);
                atomicAdd(a + 3, w  * wt);
#endif
            }
        }
    }
}

// ---------------------------------------------------------------------------
// Fused normalize + morphological open (erode kxk then dilate kxk, SAME
// padding, inf/-inf pad) + compose. Reads accumulators directly:
//   - mask values m = w/(w+eps) over the halo region (scalar .w loads)
//   - full float4 at tile centers for normalized RGB
// Writes ALL 18 output channels. One block = one 32x16 tile, both directions.
// ---------------------------------------------------------------------------
#define TTX 32
#define TTY 16
#define RMAX 4
#define INW_MAX (TTX + 4 * RMAX)   // 48
#define INH_MAX (TTY + 4 * RMAX)   // 32
#define HMW_MAX (TTX + 2 * RMAX)   // 40
#define EH_MAX  (TTY + 2 * RMAX)   // 24

__global__ void __launch_bounds__(TTX * TTY) open_compose_kernel(
    const int* __restrict__ kptr,
    const float* __restrict__ flow0, const float* __restrict__ flow1,
    float* __restrict__ out)
{
    __shared__ float s_in[2][INH_MAX][INW_MAX];
    __shared__ float s_hm[2][INH_MAX][HMW_MAX];
    __shared__ float s_er[2][EH_MAX][HMW_MAX];
    __shared__ float s_hx[2][EH_MAX][TTX];

    const float PINF = __int_as_float(0x7f800000);
    const float NINF = __int_as_float(0xff800000);

    int kk = kptr[0];
    int r = (kk >= 2) ? (kk - 1) / 2 : 0;
    if (r > RMAX) r = RMAX;

    int b  = blockIdx.z;
    int ox = blockIdx.x * TTX;
    int oy = blockIdx.y * TTY;
    int tid = threadIdx.y * TTX + threadIdx.x;
    const int NT = TTX * TTY;

    int inw = TTX + 4 * r, inh = TTY + 4 * r;
    int hmw = TTX + 2 * r, eh = TTY + 2 * r;
    int win = 2 * r;  // extra taps beyond center

    // --- Center loads: full float4 accumulators for this thread's pixel ---
    int txx = threadIdx.x, tyy = threadIdx.y;
    int gx = ox + txx, gy = oy + tyy;
    bool inimg = (gx < WW) && (gy < HH);
    size_t p = (size_t)gy * WW + gx;
    float4 a0 = make_float4(0.f, 0.f, 0.f, 0.f);
    float4 a1 = a0;
    if (inimg) {
        a0 = reinterpret_cast<const float4*>(g_acc)[(size_t)(0 * BB + b) * HW + p];
        a1 = reinterpret_cast<const float4*>(g_acc)[(size_t)(1 * BB + b) * HW + p];
    }
    float i0 = 1.0f / (a0.w + EPSF);
    float i1 = 1.0f / (a1.w + EPSF);
    float f01r = a0.x * i0, f01g = a0.y * i0, f01b = a0.z * i0;
    float f10r = a1.x * i1, f10g = a1.y * i1, f10b = a1.z * i1;

    // --- Halo mask loads: m = w/(w+eps); +inf outside image (erosion pad) ---
    for (int idx = tid; idx < 2 * inh * inw; idx += NT) {
        int m = idx / (inh * inw);
        int rem = idx - m * inh * inw;
        int iy = rem / inw;
        int ix = rem - iy * inw;
        int hy = oy - 2 * r + iy;
        int hx = ox - 2 * r + ix;
        float v = PINF;
        if ((unsigned)hy < (unsigned)HH && (unsigned)hx < (unsigned)WW) {
            float wv = g_acc[(((size_t)(m * BB + b) * HW + (size_t)hy * WW + hx) << 2) + 3];
            v = wv / (wv + EPSF);
        }
        s_in[m][iy][ix] = v;
    }
    __syncthreads();

    // Horizontal min
    for (int idx = tid; idx < 2 * inh * hmw; idx += NT) {
        int m = idx / (inh * hmw);
        int rem = idx - m * inh * hmw;
        int iy = rem / hmw;
        int hx = rem - iy * hmw;
        float v = s_in[m][iy][hx];
        for (int dd = 1; dd <= win; ++dd) v = fminf(v, s_in[m][iy][hx + dd]);
        s_hm[m][iy][hx] = v;
    }
    __syncthreads();

    // Vertical min -> erosion; out-of-image -> -inf (dilation pad)
    for (int idx = tid; idx < 2 * eh * hmw; idx += NT) {
        int m = idx / (eh * hmw);
        int rem = idx - m * eh * hmw;
        int ey = rem / hmw;
        int hx = rem - ey * hmw;
        int hy = oy - r + ey;
        int hgx = ox - r + hx;
        float v = NINF;
        if ((unsigned)hy < (unsigned)HH && (unsigned)hgx < (unsigned)WW) {
            v = s_hm[m][ey][hx];
            for (int dd = 1; dd <= win; ++dd) v = fminf(v, s_hm[m][ey + dd][hx]);
        }
        s_er[m][ey][hx] = v;
    }
    __syncthreads();

    // Horizontal max
    for (int idx = tid; idx < 2 * eh * TTX; idx += NT) {
        int m = idx / (eh * TTX);
        int rem = idx - m * eh * TTX;
        int ey = rem / TTX;
        int xx = rem - ey * TTX;
        float v = s_er[m][ey][xx];
        for (int dd = 1; dd <= win; ++dd) v = fmaxf(v, s_er[m][ey][xx + dd]);
        s_hx[m][ey][xx] = v;
    }
    __syncthreads();

    // Vertical max -> opened masks; compose and write all 18 channels
    if (inimg) {
        float m01 = s_hx[0][tyy][txx];
        float m10 = s_hx[1][tyy][txx];
        for (int dd = 1; dd <= win; ++dd) {
            m01 = fmaxf(m01, s_hx[0][tyy + dd][txx]);
            m10 = fmaxf(m10, s_hx[1][tyy + dd][txx]);
        }
        float* ob = out + (size_t)b * 18 * HW;
        ob[(size_t)0  * HW + p] = m01 * f01r + (1.0f - m01) * f10r;
        ob[(size_t)1  * HW + p] = m01 * f01g + (1.0f - m01) * f10g;
        ob[(size_t)2  * HW + p] = m01 * f01b + (1.0f - m01) * f10b;
        ob[(size_t)3  * HW + p] = m10 * f10r + (1.0f - m10) * f01r;
        ob[(size_t)4  * HW + p] = m10 * f10g + (1.0f - m10) * f01g;
        ob[(size_t)5  * HW + p] = m10 * f10b + (1.0f - m10) * f01b;
        ob[(size_t)6  * HW + p] = f01r;
        ob[(size_t)7  * HW + p] = f01g;
        ob[(size_t)8  * HW + p] = f01b;
        ob[(size_t)9  * HW + p] = f10r;
        ob[(size_t)10 * HW + p] = f10g;
        ob[(size_t)11 * HW + p] = f10b;
        ob[(size_t)12 * HW + p] = 0.5f * flow0[(size_t)(b * 2 + 0) * HW + p];
        ob[(size_t)13 * HW + p] = 0.5f * flow0[(size_t)(b * 2 + 1) * HW + p];
        ob[(size_t)14 * HW + p] = 0.5f * flow1[(size_t)(b * 2 + 0) * HW + p];
        ob[(size_t)15 * HW + p] = 0.5f * flow1[(size_t)(b * 2 + 1) * HW + p];
        ob[(size_t)16 * HW + p] = m01;
        ob[(size_t)17 * HW + p] = m10;
    }
}

// ---------------------------------------------------------------------------
extern "C" void kernel_launch(void* const* d_in, const int* in_sizes, int n_in,
                              void* d_out, int out_size)
{
    const float* img0  = (const float*)d_in[0];
    const float* img1  = (const float*)d_in[1];
    const float* flow0 = (const float*)d_in[2];
    const float* flow1 = (const float*)d_in[3];
    const float* z0    = (const float*)d_in[4];
    const float* z1    = (const float*)d_in[5];
    const int*   kptr  = (const int*)d_in[6];
    float* out = (float*)d_out;

    // Clear accumulators (memset node in the captured graph)
    void* accPtr = nullptr;
    cudaGetSymbolAddress(&accPtr, g_acc);
    cudaMemsetAsync(accPtr, 0, sizeof(float) * (size_t)2 * BB * HW * 4, 0);

    int threads = 256;
    int blocks = (NPIX + threads - 1) / threads;
    splat_kernel<<<blocks, threads>>>(img0, img1, flow0, flow1, z0, z1);

    dim3 gblk(TTX, TTY, 1);
    dim3 ggrid((WW + TTX - 1) / TTX, (HH + TTY - 1) / TTY, BB);
    open_compose_kernel<<<ggrid, gblk>>>(kptr, flow0, flow1, out);
}

// round 3
// speedup vs baseline: 2.5184x; 1.1456x over previous
#include <cuda_runtime.h>
#include <math.h>

#define BB 2
#define HH 720
#define WW 1280
#define HW (HH*WW)
#define NPIX (BB*HW)
#define EPSF 1e-7f

// Scratch: splat accumulators [dir][b][pixel][4ch]  (~59 MB)
__device__ __align__(16) float g_acc[(size_t)2 * BB * HW * 4];

// ---------------------------------------------------------------------------
// Splat kernel: each thread handles one source pixel, both warp directions.
// sm_90+ float4 atomicAdd -> one RED.E.128 per corner.
// ---------------------------------------------------------------------------
__global__ void __launch_bounds__(256) splat_kernel(
    const float* __restrict__ img0, const float* __restrict__ img1,
    const float* __restrict__ flow0, const float* __restrict__ flow1,
    const float* __restrict__ z0, const float* __restrict__ z1)
{
    int i = blockIdx.x * blockDim.x + threadIdx.x;
    if (i >= NPIX) return;
    int b = i / HW;
    int p = i - b * HW;
    int y = p / WW;
    int x = p - y * WW;

#pragma unroll
    for (int d = 0; d < 2; ++d) {
        const float* img = d ? img1 : img0;
        const float* fl  = d ? flow0 : flow1;
        const float* zz  = d ? z0 : z1;

        float fx = (float)x + 0.5f * fl[(size_t)(b * 2 + 1) * HW + p];
        float fy = (float)y + 0.5f * fl[(size_t)(b * 2 + 0) * HW + p];
        float w  = __expf(zz[(size_t)b * HW + p]);
        float vr = img[(size_t)(b * 3 + 0) * HW + p] * w;
        float vg = img[(size_t)(b * 3 + 1) * HW + p] * w;
        float vb = img[(size_t)(b * 3 + 2) * HW + p] * w;

        float x0f = floorf(fx), y0f = floorf(fy);
        int ix0 = (int)x0f, iy0 = (int)y0f;
        float ax = fx - x0f, ay = fy - y0f;

        float4* acc = reinterpret_cast<float4*>(g_acc) + (size_t)(d * BB + b) * HW;
#pragma unroll
        for (int cy = 0; cy < 2; ++cy) {
            int ty = iy0 + cy;
            if ((unsigned)ty >= (unsigned)HH) continue;
            float wy = cy ? ay : (1.0f - ay);
#pragma unroll
            for (int cx = 0; cx < 2; ++cx) {
                int tx = ix0 + cx;
                if ((unsigned)tx >= (unsigned)WW) continue;
                float wt = wy * (cx ? ax : (1.0f - ax));
                atomicAdd(acc + ((size_t)ty * WW + tx),
                          make_float4(vr * wt, vg * wt, vb * wt, w * wt));
            }
        }
    }
}

// ---------------------------------------------------------------------------
// Fused normalize + morphological open + compose, fully template-specialized
// on the radius R so every loop bound / division is compile-time constant.
// One block = one 32x16 output tile, both warp directions.
// ---------------------------------------------------------------------------
#define TTX 32
#define TTY 16
#define RMAX 4
#define INW_MAX (TTX + 4 * RMAX)   // 48
#define INH_MAX (TTY + 4 * RMAX)   // 32
#define HMW_MAX (TTX + 2 * RMAX)   // 40
#define EH_MAX  (TTY + 2 * RMAX)   // 24
#define NT (TTX * TTY)

struct SmemT {
    float s_in[2][INH_MAX][INW_MAX];
    float s_hm[2][INH_MAX][HMW_MAX];
    float s_er[2][EH_MAX][HMW_MAX];
    float s_hx[2][EH_MAX][TTX];
};

template<int R>
__device__ __forceinline__ void open_body(
    SmemT& S,
    const float* __restrict__ flow0, const float* __restrict__ flow1,
    float* __restrict__ out)
{
    constexpr int INW = TTX + 4 * R;
    constexpr int INH = TTY + 4 * R;
    constexpr int HMW = TTX + 2 * R;
    constexpr int EH  = TTY + 2 * R;
    constexpr int WIN = 2 * R;

    const float PINF = __int_as_float(0x7f800000);
    const float NINF = __int_as_float(0xff800000);

    int b  = blockIdx.z;
    int ox = blockIdx.x * TTX;
    int oy = blockIdx.y * TTY;
    int tid = threadIdx.y * TTX + threadIdx.x;

    // --- Center loads: full float4 accumulators for this thread's pixel ---
    int txx = threadIdx.x, tyy = threadIdx.y;
    int gx = ox + txx, gy = oy + tyy;
    bool inimg = (gx < WW) && (gy < HH);
    size_t p = (size_t)gy * WW + gx;
    float4 a0 = make_float4(0.f, 0.f, 0.f, 0.f);
    float4 a1 = a0;
    if (inimg) {
        a0 = reinterpret_cast<const float4*>(g_acc)[(size_t)(0 * BB + b) * HW + p];
        a1 = reinterpret_cast<const float4*>(g_acc)[(size_t)(1 * BB + b) * HW + p];
    }
    float i0 = 1.0f / (a0.w + EPSF);
    float i1 = 1.0f / (a1.w + EPSF);
    float f01r = a0.x * i0, f01g = a0.y * i0, f01b = a0.z * i0;
    float f10r = a1.x * i1, f10g = a1.y * i1, f10b = a1.z * i1;

    // --- Halo mask loads: m = w/(w+eps); +inf outside image (erosion pad) ---
#pragma unroll
    for (int m = 0; m < 2; ++m) {
        const float* wbase = g_acc + ((size_t)(m * BB + b) * HW << 2) + 3;
#pragma unroll 2
        for (int idx = tid; idx < INH * INW; idx += NT) {
            int iy = idx / INW;
            int ix = idx - iy * INW;
            int hy = oy - 2 * R + iy;
            int hx = ox - 2 * R + ix;
            float v = PINF;
            if ((unsigned)hy < (unsigned)HH && (unsigned)hx < (unsigned)WW) {
                float wv = wbase[((size_t)hy * WW + hx) << 2];
                v = wv / (wv + EPSF);
            }
            S.s_in[m][iy][ix] = v;
        }
    }
    __syncthreads();

    // Horizontal min
#pragma unroll
    for (int m = 0; m < 2; ++m) {
#pragma unroll 2
        for (int idx = tid; idx < INH * HMW; idx += NT) {
            int iy = idx / HMW;
            int hx = idx - iy * HMW;
            float v = S.s_in[m][iy][hx];
#pragma unroll
            for (int dd = 1; dd <= WIN; ++dd) v = fminf(v, S.s_in[m][iy][hx + dd]);
            S.s_hm[m][iy][hx] = v;
        }
    }
    __syncthreads();

    // Vertical min -> erosion; out-of-image -> -inf (dilation pad)
#pragma unroll
    for (int m = 0; m < 2; ++m) {
#pragma unroll 2
        for (int idx = tid; idx < EH * HMW; idx += NT) {
            int ey = idx / HMW;
            int hx = idx - ey * HMW;
            int hy = oy - R + ey;
            int hgx = ox - R + hx;
            float v = NINF;
            if ((unsigned)hy < (unsigned)HH && (unsigned)hgx < (unsigned)WW) {
                v = S.s_hm[m][ey][hx];
#pragma unroll
                for (int dd = 1; dd <= WIN; ++dd) v = fminf(v, S.s_hm[m][ey + dd][hx]);
            }
            S.s_er[m][ey][hx] = v;
        }
    }
    __syncthreads();

    // Horizontal max
#pragma unroll
    for (int m = 0; m < 2; ++m) {
#pragma unroll 2
        for (int idx = tid; idx < EH * TTX; idx += NT) {
            int ey = idx / TTX;
            int xx = idx - ey * TTX;
            float v = S.s_er[m][ey][xx];
#pragma unroll
            for (int dd = 1; dd <= WIN; ++dd) v = fmaxf(v, S.s_er[m][ey][xx + dd]);
            S.s_hx[m][ey][xx] = v;
        }
    }
    __syncthreads();

    // Vertical max -> opened masks; compose and write all 18 channels
    if (inimg) {
        float m01 = S.s_hx[0][tyy][txx];
        float m10 = S.s_hx[1][tyy][txx];
#pragma unroll
        for (int dd = 1; dd <= WIN; ++dd) {
            m01 = fmaxf(m01, S.s_hx[0][tyy + dd][txx]);
            m10 = fmaxf(m10, S.s_hx[1][tyy + dd][txx]);
        }
        float* ob = out + (size_t)b * 18 * HW;
        ob[(size_t)0  * HW + p] = m01 * f01r + (1.0f - m01) * f10r;
        ob[(size_t)1  * HW + p] = m01 * f01g + (1.0f - m01) * f10g;
        ob[(size_t)2  * HW + p] = m01 * f01b + (1.0f - m01) * f10b;
        ob[(size_t)3  * HW + p] = m10 * f10r + (1.0f - m10) * f01r;
        ob[(size_t)4  * HW + p] = m10 * f10g + (1.0f - m10) * f01g;
        ob[(size_t)5  * HW + p] = m10 * f10b + (1.0f - m10) * f01b;
        ob[(size_t)6  * HW + p] = f01r;
        ob[(size_t)7  * HW + p] = f01g;
        ob[(size_t)8  * HW + p] = f01b;
        ob[(size_t)9  * HW + p] = f10r;
        ob[(size_t)10 * HW + p] = f10g;
        ob[(size_t)11 * HW + p] = f10b;
        ob[(size_t)12 * HW + p] = 0.5f * flow0[(size_t)(b * 2 + 0) * HW + p];
        ob[(size_t)13 * HW + p] = 0.5f * flow0[(size_t)(b * 2 + 1) * HW + p];
        ob[(size_t)14 * HW + p] = 0.5f * flow1[(size_t)(b * 2 + 0) * HW + p];
        ob[(size_t)15 * HW + p] = 0.5f * flow1[(size_t)(b * 2 + 1) * HW + p];
        ob[(size_t)16 * HW + p] = m01;
        ob[(size_t)17 * HW + p] = m10;
    }
}

__global__ void __launch_bounds__(NT) open_compose_kernel(
    const int* __restrict__ kptr,
    const float* __restrict__ flow0, const float* __restrict__ flow1,
    float* __restrict__ out)
{
    __shared__ SmemT S;

    int kk = kptr[0];
    int r = (kk >= 2) ? (kk - 1) / 2 : 0;
    if (r > RMAX) r = RMAX;

    switch (r) {
        case 0: open_body<0>(S, flow0, flow1, out); break;
        case 1: open_body<1>(S, flow0, flow1, out); break;
        case 2: open_body<2>(S, flow0, flow1, out); break;
        case 3: open_body<3>(S, flow0, flow1, out); break;
        default: open_body<4>(S, flow0, flow1, out); break;
    }
}

// ---------------------------------------------------------------------------
extern "C" void kernel_launch(void* const* d_in, const int* in_sizes, int n_in,
                              void* d_out, int out_size)
{
    const float* img0  = (const float*)d_in[0];
    const float* img1  = (const float*)d_in[1];
    const float* flow0 = (const float*)d_in[2];
    const float* flow1 = (const float*)d_in[3];
    const float* z0    = (const float*)d_in[4];
    const float* z1    = (const float*)d_in[5];
    const int*   kptr  = (const int*)d_in[6];
    float* out = (float*)d_out;

    // Clear accumulators (memset node in the captured graph)
    void* accPtr = nullptr;
    cudaGetSymbolAddress(&accPtr, g_acc);
    cudaMemsetAsync(accPtr, 0, sizeof(float) * (size_t)2 * BB * HW * 4, 0);

    int threads = 256;
    int blocks = (NPIX + threads - 1) / threads;
    splat_kernel<<<blocks, threads>>>(img0, img1, flow0, flow1, z0, z1);

    dim3 gblk(TTX, TTY, 1);
    dim3 ggrid((WW + TTX - 1) / TTX, (HH + TTY - 1) / TTY, BB);
    open_compose_kernel<<<ggrid, gblk>>>(kptr, flow0, flow1, out);
}